// round 3
// baseline (speedup 1.0000x reference)
#include <cuda_runtime.h>
#include <math.h>

#define BB 2048
#define KK 8
#define OO 256
#define II 512

#define G  8              // o's per block (one per warp)
#define OT (OO / G)       // 32 o-tiles
#define P  4              // b-slices per (k, o-tile)

// Scratch (no allocs allowed)
__device__ int g_cnt[KK];
__device__ int g_list[KK][BB];

// ---------------------------------------------------------------------------
// 0) zero the per-k counters (graph-capturable, deterministic)
// ---------------------------------------------------------------------------
__global__ void zero_kernel() {
    if (threadIdx.x < KK) g_cnt[threadIdx.x] = 0;
}

// ---------------------------------------------------------------------------
// 1) per-row argmax of gumbel-perturbed logits (hard gumbel-softmax forward
//    value is exactly this one-hot) + compaction into per-k batch lists.
//    List order is nondeterministic but output values don't depend on it.
// ---------------------------------------------------------------------------
__global__ void sel_kernel(const float* __restrict__ mw,
                           const float* __restrict__ u) {
    int b = blockIdx.x * blockDim.x + threadIdx.x;
    if (b >= BB) return;
    float best = -INFINITY;
    int   bi   = 0;
#pragma unroll
    for (int k = 0; k < KK; k++) {
        float uv = u[b * KK + k];
        float g  = -logf(-logf(uv + 1e-10f) + 1e-10f);
        float v  = mw[k] + g;
        if (v > best) { best = v; bi = k; }   // strict > == first max (jnp.argmax)
    }
    int pos = atomicAdd(&g_cnt[bi], 1);
    g_list[bi][pos] = b;
}

// ---------------------------------------------------------------------------
// 2) out[b,o] = sum_i X[b,i] * (mean[k,o,i] + exp(ls[k,o,i])*eps[b,o,i])
//    Block = (k, o-tile of G, b-slice). mean/exp(ls) live in smem for the
//    whole block (read once from DRAM) -> L2 traffic collapses to ~eps only.
//    Warp w owns o = o0+w; streams eps rows; no syncs inside the b loop.
// ---------------------------------------------------------------------------
__global__ __launch_bounds__(256)
void main_kernel(const float* __restrict__ X,
                 const float* __restrict__ mean,
                 const float* __restrict__ ls,
                 const float* __restrict__ eps,
                 float*       __restrict__ out) {
    const int blk   = blockIdx.x;
    const int slice = blk % P;
    const int ot    = (blk / P) % OT;
    const int k     = blk / (P * OT);
    const int o0    = ot * G;

    __shared__ float sm[G][II];
    __shared__ float ss[G][II];

    for (int i = threadIdx.x; i < G * II; i += 256) {
        const int o  = i / II;
        const int ii = i - o * II;
        const size_t base = ((size_t)k * OO + o0 + o) * II + ii;
        sm[o][ii] = mean[base];
        ss[o][ii] = expf(ls[base]);
    }
    __syncthreads();

    const int warp = threadIdx.x >> 5;
    const int lane = threadIdx.x & 31;
    const int o    = o0 + warp;

    const float4* smv = reinterpret_cast<const float4*>(sm[warp]);
    const float4* ssv = reinterpret_cast<const float4*>(ss[warp]);

    const int cnt   = g_cnt[k];
    const int start = (int)((long long)cnt * slice / P);
    const int end   = (int)((long long)cnt * (slice + 1) / P);

    for (int idx = start; idx < end; idx++) {
        const int b = g_list[k][idx];
        const float4* Xv = reinterpret_cast<const float4*>(X + (size_t)b * II);
        const float4* ev = reinterpret_cast<const float4*>(eps + ((size_t)b * OO + o) * II);

        float acc = 0.f;
#pragma unroll
        for (int j = 0; j < 4; j++) {
            const int t = lane + j * 32;
            const float4 x4 = __ldg(&Xv[t]);
            const float4 e4 = ev[t];
            const float4 m4 = smv[t];
            const float4 s4 = ssv[t];
            acc += x4.x * fmaf(s4.x, e4.x, m4.x);
            acc += x4.y * fmaf(s4.y, e4.y, m4.y);
            acc += x4.z * fmaf(s4.z, e4.z, m4.z);
            acc += x4.w * fmaf(s4.w, e4.w, m4.w);
        }
#pragma unroll
        for (int off = 16; off; off >>= 1)
            acc += __shfl_xor_sync(0xffffffffu, acc, off);

        if (lane == 0) out[(size_t)b * OO + o] = acc;
    }
}

// ---------------------------------------------------------------------------
// Inputs (metadata order): X[B,I], mix_weights[K], mean[K,O,I],
//                          log_sigma[K,O,I], u_gumbel[B,K], eps[B,O,I]
// Output: float32 [B,O]
// ---------------------------------------------------------------------------
extern "C" void kernel_launch(void* const* d_in, const int* in_sizes, int n_in,
                              void* d_out, int out_size) {
    const float* X    = (const float*)d_in[0];
    const float* mw   = (const float*)d_in[1];
    const float* mean = (const float*)d_in[2];
    const float* ls   = (const float*)d_in[3];
    const float* u    = (const float*)d_in[4];
    const float* eps  = (const float*)d_in[5];
    float* out        = (float*)d_out;

    zero_kernel<<<1, 32>>>();
    sel_kernel<<<(BB + 255) / 256, 256>>>(mw, u);
    main_kernel<<<KK * OT * P, 256>>>(X, mean, ls, eps, out);
}

// round 4
// speedup vs baseline: 1.2213x; 1.2213x over previous
#include <cuda_runtime.h>
#include <math.h>

#define BB 2048
#define KK 8
#define OO 256
#define II 512

#define G  8              // o's per block (one warp each)
#define OT (OO / G)       // 32 o-tiles
#define P  4              // b-slices per (k, o-tile)

// Scratch (no allocs allowed)
__device__ int g_cnt[KK];
__device__ int g_list[KK][BB];

// ---------------------------------------------------------------------------
// 0) zero per-k counters
// ---------------------------------------------------------------------------
__global__ void zero_kernel() {
    if (threadIdx.x < KK) g_cnt[threadIdx.x] = 0;
}

// ---------------------------------------------------------------------------
// 1) argmax of gumbel-perturbed logits (== hard gumbel-softmax forward
//    one-hot) + compaction into per-k batch lists. List order is
//    nondeterministic but each output value is order-independent.
// ---------------------------------------------------------------------------
__global__ void sel_kernel(const float* __restrict__ mw,
                           const float* __restrict__ u) {
    int b = blockIdx.x * blockDim.x + threadIdx.x;
    if (b >= BB) return;
    float best = -INFINITY;
    int   bi   = 0;
#pragma unroll
    for (int k = 0; k < KK; k++) {
        float uv = u[b * KK + k];
        float g  = -logf(-logf(uv + 1e-10f) + 1e-10f);
        float v  = mw[k] + g;
        if (v > best) { best = v; bi = k; }   // strict > == first max (jnp.argmax)
    }
    int pos = atomicAdd(&g_cnt[bi], 1);
    g_list[bi][pos] = b;
}

// ---------------------------------------------------------------------------
// 2) out[b,o] = sum_i X[b,i] * fmaf(exp(ls[k,o,i]), eps[b,o,i], mean[k,o,i])
//    Warp owns a FIXED (k,o): std and mean rows live in REGISTERS
//    (16 floats each per lane, loaded once). Inner loop per b is exactly
//    8 LDG.128 (4 eps from DRAM + 4 X from L1) + 32 FFMA + shuffle-reduce.
//    No smem, no LDS in the hot loop -> LSU floor halved vs previous rev.
// ---------------------------------------------------------------------------
__global__ __launch_bounds__(256, 2)
void main_kernel(const float* __restrict__ X,
                 const float* __restrict__ mean,
                 const float* __restrict__ ls,
                 const float* __restrict__ eps,
                 float*       __restrict__ out) {
    const int blk   = blockIdx.x;
    const int slice = blk % P;
    const int ot    = (blk / P) % OT;
    const int k     = blk / (P * OT);

    const int warp = threadIdx.x >> 5;
    const int lane = threadIdx.x & 31;
    const int o    = ot * G + warp;

    // Prologue: (k,o) row of mean and exp(log_sigma) into registers.
    const size_t rbase = ((size_t)k * OO + o) * II;
    const float4* mrow = reinterpret_cast<const float4*>(mean + rbase);
    const float4* lrow = reinterpret_cast<const float4*>(ls   + rbase);

    float4 mv[4], sv[4];
#pragma unroll
    for (int j = 0; j < 4; j++) {
        mv[j] = mrow[lane + 32 * j];
        float4 l4 = lrow[lane + 32 * j];
        sv[j].x = expf(l4.x); sv[j].y = expf(l4.y);
        sv[j].z = expf(l4.z); sv[j].w = expf(l4.w);
    }

    const int cnt   = g_cnt[k];
    const int start = (int)((long long)cnt * slice / P);
    const int end   = (int)((long long)cnt * (slice + 1) / P);

    for (int idx = start; idx < end; idx++) {
        const int b = g_list[k][idx];
        const float4* Xv = reinterpret_cast<const float4*>(X + (size_t)b * II);
        const float4* ev = reinterpret_cast<const float4*>(eps + ((size_t)b * OO + o) * II);

        // Batch all 8 LDG.128 up front for max MLP.
        float4 x4[4], e4[4];
#pragma unroll
        for (int j = 0; j < 4; j++) {
            x4[j] = Xv[lane + 32 * j];
            e4[j] = ev[lane + 32 * j];
        }

        float acc = 0.f;
#pragma unroll
        for (int j = 0; j < 4; j++) {
            acc = fmaf(x4[j].x, fmaf(sv[j].x, e4[j].x, mv[j].x), acc);
            acc = fmaf(x4[j].y, fmaf(sv[j].y, e4[j].y, mv[j].y), acc);
            acc = fmaf(x4[j].z, fmaf(sv[j].z, e4[j].z, mv[j].z), acc);
            acc = fmaf(x4[j].w, fmaf(sv[j].w, e4[j].w, mv[j].w), acc);
        }
#pragma unroll
        for (int off = 16; off; off >>= 1)
            acc += __shfl_xor_sync(0xffffffffu, acc, off);

        if (lane == 0) out[(size_t)b * OO + o] = acc;
    }
}

// ---------------------------------------------------------------------------
// Inputs (metadata order): X[B,I], mix_weights[K], mean[K,O,I],
//                          log_sigma[K,O,I], u_gumbel[B,K], eps[B,O,I]
// Output: float32 [B,O]
// ---------------------------------------------------------------------------
extern "C" void kernel_launch(void* const* d_in, const int* in_sizes, int n_in,
                              void* d_out, int out_size) {
    const float* X    = (const float*)d_in[0];
    const float* mw   = (const float*)d_in[1];
    const float* mean = (const float*)d_in[2];
    const float* ls   = (const float*)d_in[3];
    const float* u    = (const float*)d_in[4];
    const float* eps  = (const float*)d_in[5];
    float* out        = (float*)d_out;

    zero_kernel<<<1, 32>>>();
    sel_kernel<<<(BB + 255) / 256, 256>>>(mw, u);
    main_kernel<<<KK * OT * P, 256>>>(X, mean, ls, eps, out);
}